// round 1
// baseline (speedup 1.0000x reference)
#include <cuda_runtime.h>
#include <math.h>
#include <stdint.h>

// Problem constants
#define Bb   4
#define SS   4096
#define HH   2048
#define DFFC 8192
#define BSZ  (Bb*SS)          // 16384 tokens
#define EPS_F 1e-5f

typedef unsigned long long ull;

// ---------------- scratch (device globals; no allocation allowed) ----------
__device__ float g_logits[BSZ];
__device__ float g_r1[BSZ];
__device__ float g_thr[Bb];
__device__ int   g_sel[BSZ];
__device__ int   g_nsel;
__device__ float g_Wcomb[(size_t)HH*HH];        // diag(n1w)*Wv*Wo
__device__ float g_res[(size_t)BSZ*HH];         // residual for selected tokens
__device__ float g_r2[BSZ];
__device__ float g_hbuf[(size_t)BSZ*DFFC];      // silu(gate)*up

// ---------------- f32x2 helpers -------------------------------------------
__device__ __forceinline__ void ffma2(ull &c, ull a, ull b){
    asm("fma.rn.f32x2 %0,%1,%2,%0;" : "+l"(c) : "l"(a), "l"(b));
}
__device__ __forceinline__ ull pack2(float v){
    ull r; asm("mov.b64 %0,{%1,%1};" : "=l"(r) : "f"(v)); return r;
}
__device__ __forceinline__ float2 unpack2(ull v){
    float2 r; asm("mov.b64 {%0,%1},%2;" : "=f"(r.x), "=f"(r.y) : "l"(v)); return r;
}

// ---------------- router: logits (fp64 accum) + rmsnorm1 scale -------------
__global__ __launch_bounds__(256) void k_router(const float* __restrict__ x,
        const float* __restrict__ wr, const float* __restrict__ br){
    int t = blockIdx.x;
    const float* xr = x + (size_t)t*HH;
    double ds = 0.0; float ssq = 0.f;
    for (int i = threadIdx.x; i < HH; i += 256){
        float v = xr[i];
        ds += (double)v * (double)wr[i];
        ssq += v*v;
    }
    __shared__ double sd[256];
    __shared__ float  sf[256];
    sd[threadIdx.x] = ds; sf[threadIdx.x] = ssq;
    __syncthreads();
    for (int o = 128; o > 0; o >>= 1){
        if (threadIdx.x < o){ sd[threadIdx.x] += sd[threadIdx.x+o]; sf[threadIdx.x] += sf[threadIdx.x+o]; }
        __syncthreads();
    }
    if (threadIdx.x == 0){
        g_logits[t] = (float)(sd[0] + (double)br[0]);
        g_r1[t]     = rsqrtf(sf[0]*(1.f/HH) + EPS_F);
    }
}

// ---------------- per-batch threshold via bitonic sort ---------------------
__global__ __launch_bounds__(1024) void k_topk(){
    __shared__ float s[SS];
    int b = blockIdx.x, tid = threadIdx.x;
    for (int i = tid; i < SS; i += 1024) s[i] = g_logits[b*SS + i];
    __syncthreads();
    for (int k = 2; k <= SS; k <<= 1){
        for (int j = k >> 1; j > 0; j >>= 1){
            for (int i = tid; i < SS; i += 1024){
                int ixj = i ^ j;
                if (ixj > i){
                    float a = s[i], c = s[ixj];
                    bool up = ((i & k) == 0);
                    if ((a > c) == up){ s[i] = c; s[ixj] = a; }
                }
            }
            __syncthreads();
        }
    }
    if (tid == 0) g_thr[b] = s[SS/2];   // k-th largest of 4096, k=2048
}

__global__ void k_zero(){ g_nsel = 0; }

__global__ __launch_bounds__(256) void k_compact(){
    int t = blockIdx.x*256 + threadIdx.x;
    if (t < BSZ && g_logits[t] >= g_thr[t/SS]){
        int p = atomicAdd(&g_nsel, 1);
        g_sel[p] = t;
    }
}

// ---------------- GEMM cores: 128x128x16 tiles, 256 thr, 8x8/thr, f32x2 ----
// K4: Wcomb = diag(n1w)*Wv @ Wo   (M=N=K=2048)
__global__ __launch_bounds__(256,2) void k_wcomb(const float* __restrict__ Wv,
        const float* __restrict__ Wo, const float* __restrict__ n1w){
    __shared__ float As[16][128];
    __shared__ float Bs[16][128];
    int tid = threadIdx.x, tx = tid & 15, ty = tid >> 4;
    int m0 = blockIdx.y*128, n0 = blockIdx.x*128;

    const float* ar[2]; float asc[2];
    const float* brp[2]; int brr[2];
    #pragma unroll
    for (int l = 0; l < 2; l++){
        int q = tid*2 + l;
        { int r = q >> 2; ar[l] = &Wv[(size_t)(m0+r)*HH + (q&3)*4]; asc[l] = n1w[m0+r]; }
        { int r = q >> 5; brp[l] = &Wo[(size_t)r*HH + n0 + (q&31)*4]; brr[l] = r; }
    }
    ull acc[8][4];
    #pragma unroll
    for (int i = 0; i < 8; i++)
        #pragma unroll
        for (int j = 0; j < 4; j++) acc[i][j] = 0ull;

    for (int k0 = 0; k0 < HH; k0 += 16){
        #pragma unroll
        for (int l = 0; l < 2; l++){
            int q = tid*2 + l; int r = q >> 2; int c = (q&3)*4;
            float4 v = *(const float4*)(ar[l] + k0);
            float s = asc[l];
            As[c+0][r] = v.x*s; As[c+1][r] = v.y*s; As[c+2][r] = v.z*s; As[c+3][r] = v.w*s;
        }
        #pragma unroll
        for (int l = 0; l < 2; l++){
            int q = tid*2 + l; int c = (q&31)*4;
            float4 v = *(const float4*)(brp[l] + (size_t)k0*HH);
            *(float4*)&Bs[brr[l]][c] = v;
        }
        __syncthreads();
        #pragma unroll
        for (int kk = 0; kk < 16; kk++){
            float a8[8];
            *(float4*)a8     = *(const float4*)&As[kk][ty*8];
            *(float4*)(a8+4) = *(const float4*)&As[kk][ty*8+4];
            ull b2[4];
            const ull* bp = (const ull*)&Bs[kk][tx*8];
            b2[0]=bp[0]; b2[1]=bp[1]; b2[2]=bp[2]; b2[3]=bp[3];
            #pragma unroll
            for (int i = 0; i < 8; i++){
                ull ap = pack2(a8[i]);
                #pragma unroll
                for (int j = 0; j < 4; j++) ffma2(acc[i][j], ap, b2[j]);
            }
        }
        __syncthreads();
    }
    #pragma unroll
    for (int i = 0; i < 8; i++){
        size_t ob = (size_t)(m0 + ty*8 + i)*HH + n0 + tx*8;
        #pragma unroll
        for (int jc = 0; jc < 4; jc++){
            float2 c2 = unpack2(acc[i][jc]);
            g_Wcomb[ob + jc*2 + 0] = c2.x;
            g_Wcomb[ob + jc*2 + 1] = c2.y;
        }
    }
}

// K5: res = x_sel + r1 * (x_sel @ Wcomb)   (M=nsel, N=K=2048), gathered A
__global__ __launch_bounds__(256,2) void k_attn(const float* __restrict__ x){
    int nsel = g_nsel;
    int m0 = blockIdx.y*128; if (m0 >= nsel) return;
    int n0 = blockIdx.x*128;
    __shared__ float As[16][128];
    __shared__ float Bs[16][128];
    int tid = threadIdx.x, tx = tid & 15, ty = tid >> 4;

    const float* ar[2];
    const float* brp[2]; int brr[2];
    #pragma unroll
    for (int l = 0; l < 2; l++){
        int q = tid*2 + l;
        { int r = q >> 2; int jj = m0 + r; int t = (jj < nsel) ? g_sel[jj] : g_sel[0];
          ar[l] = &x[(size_t)t*HH + (q&3)*4]; }
        { int r = q >> 5; brp[l] = &g_Wcomb[(size_t)r*HH + n0 + (q&31)*4]; brr[l] = r; }
    }
    ull acc[8][4];
    #pragma unroll
    for (int i = 0; i < 8; i++)
        #pragma unroll
        for (int j = 0; j < 4; j++) acc[i][j] = 0ull;

    for (int k0 = 0; k0 < HH; k0 += 16){
        #pragma unroll
        for (int l = 0; l < 2; l++){
            int q = tid*2 + l; int r = q >> 2; int c = (q&3)*4;
            float4 v = *(const float4*)(ar[l] + k0);
            As[c+0][r] = v.x; As[c+1][r] = v.y; As[c+2][r] = v.z; As[c+3][r] = v.w;
        }
        #pragma unroll
        for (int l = 0; l < 2; l++){
            int q = tid*2 + l; int c = (q&31)*4;
            float4 v = *(const float4*)(brp[l] + (size_t)k0*HH);
            *(float4*)&Bs[brr[l]][c] = v;
        }
        __syncthreads();
        #pragma unroll
        for (int kk = 0; kk < 16; kk++){
            float a8[8];
            *(float4*)a8     = *(const float4*)&As[kk][ty*8];
            *(float4*)(a8+4) = *(const float4*)&As[kk][ty*8+4];
            ull b2[4];
            const ull* bp = (const ull*)&Bs[kk][tx*8];
            b2[0]=bp[0]; b2[1]=bp[1]; b2[2]=bp[2]; b2[3]=bp[3];
            #pragma unroll
            for (int i = 0; i < 8; i++){
                ull ap = pack2(a8[i]);
                #pragma unroll
                for (int j = 0; j < 4; j++) ffma2(acc[i][j], ap, b2[j]);
            }
        }
        __syncthreads();
    }
    #pragma unroll
    for (int i = 0; i < 8; i++){
        int j = m0 + ty*8 + i; if (j >= nsel) continue;
        int t = g_sel[j];
        float r1v = g_r1[t];
        size_t ob = (size_t)j*HH + n0 + tx*8;
        size_t xb = (size_t)t*HH + n0 + tx*8;
        #pragma unroll
        for (int jc = 0; jc < 4; jc++){
            float2 c2 = unpack2(acc[i][jc]);
            g_res[ob + jc*2 + 0] = x[xb + jc*2 + 0] + r1v*c2.x;
            g_res[ob + jc*2 + 1] = x[xb + jc*2 + 1] + r1v*c2.y;
        }
    }
}

// rmsnorm2 scale for selected tokens
__global__ __launch_bounds__(256) void k_r2(){
    int j = blockIdx.x; if (j >= g_nsel) return;
    const float* r = &g_res[(size_t)j*HH];
    float ssq = 0.f;
    for (int i = threadIdx.x; i < HH; i += 256){ float v = r[i]; ssq += v*v; }
    __shared__ float sf[256];
    sf[threadIdx.x] = ssq; __syncthreads();
    for (int o = 128; o > 0; o >>= 1){
        if (threadIdx.x < o) sf[threadIdx.x] += sf[threadIdx.x+o];
        __syncthreads();
    }
    if (threadIdx.x == 0) g_r2[j] = rsqrtf(sf[0]*(1.f/HH) + EPS_F);
}

// K7: mode 0 -> hbuf = silu(r2*(res @ diag(n2w)*w_gate))
//     mode 1 -> hbuf *= r2*(res @ diag(n2w)*w_up)       (M=nsel, N=8192, K=2048)
__global__ __launch_bounds__(256,2) void k_mlp1(const float* __restrict__ Wb,
        const float* __restrict__ n2w, int mode){
    int nsel = g_nsel;
    int m0 = blockIdx.y*128; if (m0 >= nsel) return;
    int n0 = blockIdx.x*128;
    __shared__ float As[16][128];
    __shared__ float Bs[16][128];
    int tid = threadIdx.x, tx = tid & 15, ty = tid >> 4;

    const float* ar[2];
    const float* brp[2]; int brr[2];
    #pragma unroll
    for (int l = 0; l < 2; l++){
        int q = tid*2 + l;
        { int r = q >> 2; int jj = m0 + r; if (jj >= nsel) jj = 0;
          ar[l] = &g_res[(size_t)jj*HH + (q&3)*4]; }
        { int r = q >> 5; brp[l] = &Wb[(size_t)r*DFFC + n0 + (q&31)*4]; brr[l] = r; }
    }
    ull acc[8][4];
    #pragma unroll
    for (int i = 0; i < 8; i++)
        #pragma unroll
        for (int j = 0; j < 4; j++) acc[i][j] = 0ull;

    for (int k0 = 0; k0 < HH; k0 += 16){
        #pragma unroll
        for (int l = 0; l < 2; l++){
            int q = tid*2 + l; int r = q >> 2; int c = (q&3)*4;
            float4 v = *(const float4*)(ar[l] + k0);
            As[c+0][r] = v.x; As[c+1][r] = v.y; As[c+2][r] = v.z; As[c+3][r] = v.w;
        }
        #pragma unroll
        for (int l = 0; l < 2; l++){
            int q = tid*2 + l; int c = (q&31)*4;
            float sc = n2w[k0 + brr[l]];
            float4 v = *(const float4*)(brp[l] + (size_t)k0*DFFC);
            v.x *= sc; v.y *= sc; v.z *= sc; v.w *= sc;
            *(float4*)&Bs[brr[l]][c] = v;
        }
        __syncthreads();
        #pragma unroll
        for (int kk = 0; kk < 16; kk++){
            float a8[8];
            *(float4*)a8     = *(const float4*)&As[kk][ty*8];
            *(float4*)(a8+4) = *(const float4*)&As[kk][ty*8+4];
            ull b2[4];
            const ull* bp = (const ull*)&Bs[kk][tx*8];
            b2[0]=bp[0]; b2[1]=bp[1]; b2[2]=bp[2]; b2[3]=bp[3];
            #pragma unroll
            for (int i = 0; i < 8; i++){
                ull ap = pack2(a8[i]);
                #pragma unroll
                for (int j = 0; j < 4; j++) ffma2(acc[i][j], ap, b2[j]);
            }
        }
        __syncthreads();
    }
    #pragma unroll
    for (int i = 0; i < 8; i++){
        int j = m0 + ty*8 + i; if (j >= nsel) continue;
        float r2v = g_r2[j];
        size_t base = (size_t)j*DFFC + n0 + tx*8;
        #pragma unroll
        for (int jc = 0; jc < 4; jc++){
            float2 c2 = unpack2(acc[i][jc]);
            float z0 = r2v*c2.x, z1 = r2v*c2.y;
            if (mode == 0){
                g_hbuf[base + jc*2 + 0] = z0 / (1.f + expf(-z0));
                g_hbuf[base + jc*2 + 1] = z1 / (1.f + expf(-z1));
            } else {
                g_hbuf[base + jc*2 + 0] *= z0;
                g_hbuf[base + jc*2 + 1] *= z1;
            }
        }
    }
}

// K8: out[sel] = res + hbuf @ w_down    (M=nsel, N=2048, K=8192)
__global__ __launch_bounds__(256,2) void k_down(const float* __restrict__ Wd,
        float* __restrict__ out){
    int nsel = g_nsel;
    int m0 = blockIdx.y*128; if (m0 >= nsel) return;
    int n0 = blockIdx.x*128;
    __shared__ float As[16][128];
    __shared__ float Bs[16][128];
    int tid = threadIdx.x, tx = tid & 15, ty = tid >> 4;

    const float* ar[2];
    const float* brp[2]; int brr[2];
    #pragma unroll
    for (int l = 0; l < 2; l++){
        int q = tid*2 + l;
        { int r = q >> 2; int jj = m0 + r; if (jj >= nsel) jj = 0;
          ar[l] = &g_hbuf[(size_t)jj*DFFC + (q&3)*4]; }
        { int r = q >> 5; brp[l] = &Wd[(size_t)r*HH + n0 + (q&31)*4]; brr[l] = r; }
    }
    ull acc[8][4];
    #pragma unroll
    for (int i = 0; i < 8; i++)
        #pragma unroll
        for (int j = 0; j < 4; j++) acc[i][j] = 0ull;

    for (int k0 = 0; k0 < DFFC; k0 += 16){
        #pragma unroll
        for (int l = 0; l < 2; l++){
            int q = tid*2 + l; int r = q >> 2; int c = (q&3)*4;
            float4 v = *(const float4*)(ar[l] + k0);
            As[c+0][r] = v.x; As[c+1][r] = v.y; As[c+2][r] = v.z; As[c+3][r] = v.w;
        }
        #pragma unroll
        for (int l = 0; l < 2; l++){
            int q = tid*2 + l; int c = (q&31)*4;
            float4 v = *(const float4*)(brp[l] + (size_t)k0*HH);
            *(float4*)&Bs[brr[l]][c] = v;
        }
        __syncthreads();
        #pragma unroll
        for (int kk = 0; kk < 16; kk++){
            float a8[8];
            *(float4*)a8     = *(const float4*)&As[kk][ty*8];
            *(float4*)(a8+4) = *(const float4*)&As[kk][ty*8+4];
            ull b2[4];
            const ull* bp = (const ull*)&Bs[kk][tx*8];
            b2[0]=bp[0]; b2[1]=bp[1]; b2[2]=bp[2]; b2[3]=bp[3];
            #pragma unroll
            for (int i = 0; i < 8; i++){
                ull ap = pack2(a8[i]);
                #pragma unroll
                for (int j = 0; j < 4; j++) ffma2(acc[i][j], ap, b2[j]);
            }
        }
        __syncthreads();
    }
    #pragma unroll
    for (int i = 0; i < 8; i++){
        int j = m0 + ty*8 + i; if (j >= nsel) continue;
        int t = g_sel[j];
        size_t rb = (size_t)j*HH + n0 + tx*8;
        size_t ob = (size_t)t*HH + n0 + tx*8;
        #pragma unroll
        for (int jc = 0; jc < 4; jc++){
            float2 c2 = unpack2(acc[i][jc]);
            out[ob + jc*2 + 0] = g_res[rb + jc*2 + 0] + c2.x;
            out[ob + jc*2 + 1] = g_res[rb + jc*2 + 1] + c2.y;
        }
    }
}

// ---------------- launch ----------------------------------------------------
extern "C" void kernel_launch(void* const* d_in, const int* in_sizes, int n_in,
                              void* d_out, int out_size){
    const float* x   = (const float*)d_in[0];
    const float* wr  = (const float*)d_in[1];
    const float* br  = (const float*)d_in[2];
    // d_in[3] = Wq, d_in[4] = Wk : dead code (softmax over size-1 axis == 1)
    const float* Wv  = (const float*)d_in[5];
    const float* Wo  = (const float*)d_in[6];
    const float* wg  = (const float*)d_in[7];
    const float* wu  = (const float*)d_in[8];
    const float* wd  = (const float*)d_in[9];
    const float* n1w = (const float*)d_in[10];
    const float* n2w = (const float*)d_in[11];
    float* out = (float*)d_out;

    // default output: out = x (unmasked tokens pass through)
    cudaMemcpyAsync(out, x, (size_t)BSZ*HH*sizeof(float),
                    cudaMemcpyDeviceToDevice, 0);

    k_router <<<BSZ, 256>>>(x, wr, br);
    k_topk   <<<Bb, 1024>>>();
    k_zero   <<<1, 1>>>();
    k_compact<<<BSZ/256, 256>>>();

    k_wcomb  <<<dim3(16, 16),  256>>>(Wv, Wo, n1w);
    k_attn   <<<dim3(16, 128), 256>>>(x);
    k_r2     <<<BSZ, 256>>>();
    k_mlp1   <<<dim3(64, 128), 256>>>(wg, n2w, 0);
    k_mlp1   <<<dim3(64, 128), 256>>>(wu, n2w, 1);
    k_down   <<<dim3(16, 128), 256>>>(wd, out);
}